// round 15
// baseline (speedup 1.0000x reference)
#include <cuda_runtime.h>
#include <cuda_bf16.h>
#include <cstdint>

// Problem constants: N=2, L=2048, EMBED=1024, HEADS=16, Dh=64
#define SEQ_LEN   2048
#define EMBED_DIM 1024
#define NTOK      4096
#define HEAD_DIM  64

// ---------------- warp-MMA helpers (verified R8-R14) ----------------
__device__ __forceinline__ uint32_t smem_u32(const void* p) {
    uint32_t a;
    asm("{ .reg .u64 t; cvta.to.shared.u64 t, %1; cvt.u32.u64 %0, t; }"
        : "=r"(a) : "l"(p));
    return a;
}
__device__ __forceinline__ void ldm_x4(uint32_t& r0, uint32_t& r1,
                                       uint32_t& r2, uint32_t& r3, uint32_t addr) {
    asm volatile("ldmatrix.sync.aligned.m8n8.x4.shared.b16 {%0,%1,%2,%3}, [%4];"
                 : "=r"(r0), "=r"(r1), "=r"(r2), "=r"(r3) : "r"(addr));
}
__device__ __forceinline__ void mma16816(float* c, const uint32_t* a, const uint32_t* b) {
    asm volatile(
        "mma.sync.aligned.m16n8k16.row.col.f32.bf16.bf16.f32 "
        "{%0,%1,%2,%3}, {%4,%5,%6,%7}, {%8,%9}, {%0,%1,%2,%3};"
        : "+f"(c[0]), "+f"(c[1]), "+f"(c[2]), "+f"(c[3])
        : "r"(a[0]), "r"(a[1]), "r"(a[2]), "r"(a[3]), "r"(b[0]), "r"(b[1]));
}
__device__ __forceinline__ void split2(float a, float b, uint32_t& h, uint32_t& l) {
    __nv_bfloat16 ha = __float2bfloat16(a), hb = __float2bfloat16(b);
    __nv_bfloat16 la = __float2bfloat16(a - __bfloat162float(ha));
    __nv_bfloat16 lb = __float2bfloat16(b - __bfloat162float(hb));
    h = (uint32_t)__bfloat16_as_ushort(ha) | ((uint32_t)__bfloat16_as_ushort(hb) << 16);
    l = (uint32_t)__bfloat16_as_ushort(la) | ((uint32_t)__bfloat16_as_ushort(lb) << 16);
}

// cp.async (sm_80 baseline PTX)
#define CPA16(sa, ga) \
    asm volatile("cp.async.cg.shared.global [%0], [%1], 16;" :: "r"(sa), "l"(ga))
#define CPA_COMMIT() asm volatile("cp.async.commit_group;" ::: "memory")
#define CPA_WAIT0()  asm volatile("cp.async.wait_group 0;" ::: "memory")

// ---------------- scratch (device globals: allocation-guard safe) ----------------
__device__ __nv_bfloat16 g_Ahi [NTOK * EMBED_DIM];   // attn output -> final GEMM A
__device__ __nv_bfloat16 g_Alo [NTOK * EMBED_DIM];
__device__ __nv_bfloat16 g_Qhi [NTOK * EMBED_DIM];   // pre-scaled by 0.125
__device__ __nv_bfloat16 g_Qlo [NTOK * EMBED_DIM];
__device__ __nv_bfloat16 g_Khi [NTOK * EMBED_DIM];
__device__ __nv_bfloat16 g_Klo [NTOK * EMBED_DIM];
__device__ __nv_bfloat16 g_Vthi[NTOK * EMBED_DIM];   // [bh][d][token]
__device__ __nv_bfloat16 g_Vtlo[NTOK * EMBED_DIM];
// pre-split weights: index 0=W_q, 1=W_k, 2=W_v, 3=W_o
__device__ __nv_bfloat16 g_Whi [4][EMBED_DIM * EMBED_DIM];
__device__ __nv_bfloat16 g_Wlo [4][EMBED_DIM * EMBED_DIM];

#define OUT_Q   0
#define OUT_K   1
#define OUT_V   2
#define OUT_EXT 4

// =================================================================================
// wsplit_kernel: split ALL FOUR weight matrices fp32 -> bf16 hi/lo in one launch.
// Same split2 as in-staging -> GEMM inputs bit-identical to R14.
// =================================================================================
__global__ void __launch_bounds__(256) wsplit_kernel(
    const float* __restrict__ w0, const float* __restrict__ w1,
    const float* __restrict__ w2, const float* __restrict__ w3)
{
    int i = blockIdx.x * 256 + threadIdx.x;   // float4 index over 4 matrices
    int m = i >> 18;                          // 2^18 float4 per 1024x1024 matrix
    int j = i & 0x3FFFF;
    const float* w = (m == 0) ? w0 : (m == 1) ? w1 : (m == 2) ? w2 : w3;
    float4 v = ((const float4*)w)[j];
    uint2 H, L;
    split2(v.x, v.y, H.x, L.x);
    split2(v.z, v.w, H.y, L.y);
    ((uint2*)g_Whi[m])[j] = H;
    ((uint2*)g_Wlo[m])[j] = L;
}

// staged pair: either (hi uint4, lo uint4) [bf16 path] or 8 raw fp32 [fp32 path]
struct U4x2 { uint4 a, b; };

// A operand: f32p != null -> 8 fp32; else 8+8 bf16 from g_Ahi/g_Alo
__device__ __forceinline__ U4x2 ld_a(const float* f32p, int row, int col_e) {
    U4x2 r;
    if (f32p) {
        const uint4* p = (const uint4*)&f32p[(size_t)row * EMBED_DIM + col_e];
        r.a = p[0]; r.b = p[1];
    } else {
        size_t o = (size_t)row * EMBED_DIM + col_e;
        r.a = *(const uint4*)&g_Ahi[o];
        r.b = *(const uint4*)&g_Alo[o];
    }
    return r;
}
__device__ __forceinline__ void st_opnd(__nv_bfloat16* shi, __nv_bfloat16* slo,
                                        uint32_t so, const U4x2& v, bool is_f32) {
    if (is_f32) {
        const float* f = (const float*)&v;
        uint4 H, L;
        split2(f[0], f[1], H.x, L.x); split2(f[2], f[3], H.y, L.y);
        split2(f[4], f[5], H.z, L.z); split2(f[6], f[7], H.w, L.w);
        *(uint4*)&shi[so] = H; *(uint4*)&slo[so] = L;
    } else {
        *(uint4*)&shi[so] = v.a; *(uint4*)&slo[so] = v.b;
    }
}

// =================================================================================
// Tensor-core GEMM (R14 2-stage pipeline) with:
//  - B/W read from PRE-SPLIT bf16 (halved W LDG bytes, no W conversion ALU)
//  - compute reorder: ldmatrix(cur) issued BEFORE STS(t+1)/LDG(t+2) so the
//    prefetch instructions fill the LDS->MMA latency window.
// Accumulation order identical to R14 -> rel_err bit-identical (2.173874e-05).
// =================================================================================
#define GBM 128
#define GBN 128
#define GKC 16
#define GST 24                    // bf16 per smem row (16 data + 8 pad)
#define GNB (EMBED_DIM / GKC)     // 64 k-blocks

__global__ void __launch_bounds__(256) gemm_mma_kernel(
    const float* __restrict__ A0, const float* __restrict__ A1, const float* __restrict__ A2,
    const float* __restrict__ bias, int out_sel_p, int wsel_p, float* ext_out)
{
    int out_sel, wsel;
    const float* Af;
    if (out_sel_p < 0) {                      // batched QKV: z = 0/1/2
        out_sel = blockIdx.z;
        wsel    = blockIdx.z;
        Af = (blockIdx.z == 0) ? A0 : (blockIdx.z == 1) ? A1 : A2;
    } else {
        out_sel = out_sel_p;
        wsel    = wsel_p;
        Af = A0;                              // null -> bf16 path (g_Ahi/g_Alo)
    }
    const bool a_f32 = (Af != nullptr);
    const __nv_bfloat16* __restrict__ Whi = g_Whi[wsel];
    const __nv_bfloat16* __restrict__ Wlo = g_Wlo[wsel];

    // 2-stage buffers: 4 arrays x 2 x 128 x 24 x 2B = 49152 B = 48KB exactly
    __shared__ __align__(16) __nv_bfloat16 sAhi[2][GBM * GST];
    __shared__ __align__(16) __nv_bfloat16 sAlo[2][GBM * GST];
    __shared__ __align__(16) __nv_bfloat16 sBhi[2][GBN * GST];
    __shared__ __align__(16) __nv_bfloat16 sBlo[2][GBN * GST];

    const int tid  = threadIdx.x;
    const int lane = tid & 31;
    const int wid  = tid >> 5;
    const int wm0  = (wid & 3) * 32;
    const int wn0  = (wid >> 2) * 64;
    const int m0   = blockIdx.y * GBM;
    const int n0   = blockIdx.x * GBN;

    const int a_r  = lane & 15;
    const int a_c8 = (lane >> 4) << 3;
    const int b_r  = (lane & 7) + (((lane >> 4) & 1) << 3);
    const int b_c8 = ((lane >> 3) & 1) << 3;

    float acc[2][8][4];
    #pragma unroll
    for (int mi = 0; mi < 2; mi++)
        #pragma unroll
        for (int ni = 0; ni < 8; ni++)
            #pragma unroll
            for (int r = 0; r < 4; r++) acc[mi][ni][r] = 0.f;

    // staging: 128 rows x 2 chunks per operand; each thread does 1 A + 1 B chunk
    const int sr  = tid >> 1;                 // row 0..127
    const int sck = (tid & 1) * 8;            // k chunk 0 or 8
    const uint32_t so = (uint32_t)(sr * GST + sck);
    const size_t wrow = (size_t)(n0 + sr) * EMBED_DIM;

    // pipeline preamble: stage block 0, then load block 1 into regs
    U4x2 rA = ld_a(Af, m0 + sr, sck);
    U4x2 rB;
    rB.a = *(const uint4*)&Whi[wrow + sck];
    rB.b = *(const uint4*)&Wlo[wrow + sck];
    st_opnd(sAhi[0], sAlo[0], so, rA, a_f32);
    st_opnd(sBhi[0], sBlo[0], so, rB, false);
    rA = ld_a(Af, m0 + sr, GKC + sck);
    rB.a = *(const uint4*)&Whi[wrow + GKC + sck];
    rB.b = *(const uint4*)&Wlo[wrow + GKC + sck];
    __syncthreads();

    for (int t = 0; t < GNB; t++) {
        const int cur = t & 1;
        const int nb  = cur ^ 1;

        // ---- issue ldmatrix for block t FIRST (prefetch below fills the window)
        uint32_t ah[2][4], al[2][4], bb[8][2];
        #pragma unroll
        for (int mi = 0; mi < 2; mi++) {
            uint32_t ad = smem_u32(&sAhi[cur][(wm0 + mi * 16 + a_r) * GST + a_c8]);
            ldm_x4(ah[mi][0], ah[mi][1], ah[mi][2], ah[mi][3], ad);
            ad = smem_u32(&sAlo[cur][(wm0 + mi * 16 + a_r) * GST + a_c8]);
            ldm_x4(al[mi][0], al[mi][1], al[mi][2], al[mi][3], ad);
        }
        #pragma unroll
        for (int np = 0; np < 4; np++) {
            uint32_t ad = smem_u32(&sBhi[cur][(wn0 + np * 16 + b_r) * GST + b_c8]);
            ldm_x4(bb[2 * np][0], bb[2 * np][1], bb[2 * np + 1][0], bb[2 * np + 1][1], ad);
        }

        // ---- stage t+1 into the free buffer; LDG t+2 into regs
        if (t + 1 < GNB) {
            st_opnd(sAhi[nb], sAlo[nb], so, rA, a_f32);
            st_opnd(sBhi[nb], sBlo[nb], so, rB, false);
        }
        if (t + 2 < GNB) {
            int kc = (t + 2) * GKC + sck;
            rA = ld_a(Af, m0 + sr, kc);
            rB.a = *(const uint4*)&Whi[wrow + kc];
            rB.b = *(const uint4*)&Wlo[wrow + kc];
        }

        // ---- compute block t (product order: hihi, lohi, hilo — unchanged)
        #pragma unroll
        for (int mi = 0; mi < 2; mi++)
            #pragma unroll
            for (int ni = 0; ni < 8; ni++) mma16816(acc[mi][ni], ah[mi], bb[ni]);
        #pragma unroll
        for (int mi = 0; mi < 2; mi++)
            #pragma unroll
            for (int ni = 0; ni < 8; ni++) mma16816(acc[mi][ni], al[mi], bb[ni]);
        #pragma unroll
        for (int np = 0; np < 4; np++) {
            uint32_t ad = smem_u32(&sBlo[cur][(wn0 + np * 16 + b_r) * GST + b_c8]);
            ldm_x4(bb[2 * np][0], bb[2 * np][1], bb[2 * np + 1][0], bb[2 * np + 1][1], ad);
        }
        #pragma unroll
        for (int mi = 0; mi < 2; mi++)
            #pragma unroll
            for (int ni = 0; ni < 8; ni++) mma16816(acc[mi][ni], ah[mi], bb[ni]);

        __syncthreads();   // gates: readers of cur done AND writers of nb done
    }

    const int er = lane >> 2;
    const int ec = (lane & 3) * 2;
    #pragma unroll
    for (int mi = 0; mi < 2; mi++) {
        #pragma unroll
        for (int ni = 0; ni < 8; ni++) {
            int row = m0 + wm0 + mi * 16 + er;
            int col = n0 + wn0 + ni * 8 + ec;
            float v00 = acc[mi][ni][0], v01 = acc[mi][ni][1];
            float v10 = acc[mi][ni][2], v11 = acc[mi][ni][3];
            if (out_sel == OUT_EXT) {
                float b0 = bias ? bias[col] : 0.f, b1 = bias ? bias[col + 1] : 0.f;
                *(float2*)&ext_out[(size_t)row * EMBED_DIM + col] = make_float2(v00 + b0, v01 + b1);
                *(float2*)&ext_out[(size_t)(row + 8) * EMBED_DIM + col] = make_float2(v10 + b0, v11 + b1);
            } else if (out_sel == OUT_V) {
                int bb_ = row >> 11, tok = row & 2047;
                int hh  = col >> 6,  dd  = col & 63;
                size_t base = ((size_t)(bb_ * 16 + hh) * 64 + dd) * SEQ_LEN + tok;
                uint32_t h0, l0, h1, l1;
                split2(v00, v10, h0, l0);
                split2(v01, v11, h1, l1);
                g_Vthi[base]               = __ushort_as_bfloat16((unsigned short)(h0 & 0xffff));
                g_Vthi[base + 8]           = __ushort_as_bfloat16((unsigned short)(h0 >> 16));
                g_Vtlo[base]               = __ushort_as_bfloat16((unsigned short)(l0 & 0xffff));
                g_Vtlo[base + 8]           = __ushort_as_bfloat16((unsigned short)(l0 >> 16));
                g_Vthi[base + SEQ_LEN]     = __ushort_as_bfloat16((unsigned short)(h1 & 0xffff));
                g_Vthi[base + SEQ_LEN + 8] = __ushort_as_bfloat16((unsigned short)(h1 >> 16));
                g_Vtlo[base + SEQ_LEN]     = __ushort_as_bfloat16((unsigned short)(l1 & 0xffff));
                g_Vtlo[base + SEQ_LEN + 8] = __ushort_as_bfloat16((unsigned short)(l1 >> 16));
            } else {
                __nv_bfloat16* hi = (out_sel == OUT_Q) ? g_Qhi : g_Khi;
                __nv_bfloat16* lo = (out_sel == OUT_Q) ? g_Qlo : g_Klo;
                float sc = (out_sel == OUT_Q) ? 0.125f : 1.f;
                uint32_t h, l;
                split2(v00 * sc, v01 * sc, h, l);
                *(uint32_t*)&hi[(size_t)row * EMBED_DIM + col] = h;
                *(uint32_t*)&lo[(size_t)row * EMBED_DIM + col] = l;
                split2(v10 * sc, v11 * sc, h, l);
                *(uint32_t*)&hi[(size_t)(row + 8) * EMBED_DIM + col] = h;
                *(uint32_t*)&lo[(size_t)(row + 8) * EMBED_DIM + col] = l;
            }
        }
    }
}

// =================================================================================
// Tensor-core flash attention (R12-R14 verified) + warp-uniform rescale skip:
// when no row's max changed, alpha == 1.0f exactly -> skipping the 32-FMUL
// o-rescale is BIT-IDENTICAL (x1.0 is IEEE identity on finite values).
// =================================================================================
#define QT 128
#define KT 32
#define KST 72
#define VST 40
#define NT (SEQ_LEN / KT)

__global__ void __launch_bounds__(256) attn_kernel(const int* __restrict__ mask)
{
    __shared__ __align__(16) __nv_bfloat16 sKhi[2][KT * KST];
    __shared__ __align__(16) __nv_bfloat16 sKlo[2][KT * KST];
    __shared__ __align__(16) __nv_bfloat16 sVhi[2][64 * VST];
    __shared__ __align__(16) __nv_bfloat16 sVlo[2][64 * VST];
    __shared__ float mk[2][KT];

    const int tid  = threadIdx.x;
    const int lane = tid & 31;
    const int wid  = tid >> 5;
    const int wm   = wid * 16;
    const int q0   = blockIdx.x * QT;
    const int b    = blockIdx.y >> 4;
    const int h    = blockIdx.y & 15;

    const int er   = lane >> 2;
    const int ec   = (lane & 3) * 2;
    const int b_r  = (lane & 7) + (((lane >> 4) & 1) << 3);
    const int b_c8 = ((lane >> 3) & 1) << 3;

    const int k_key = tid >> 3, k_c8 = (tid & 7) * 8;
    const int v_d   = tid >> 2, v_kc = (tid & 3) * 8;
    const size_t kbase = (size_t)(b * SEQ_LEN + k_key) * EMBED_DIM + h * HEAD_DIM + k_c8;
    const size_t vbase = ((size_t)(b * 16 + h) * HEAD_DIM + v_d) * SEQ_LEN + v_kc;
    uint32_t aKhi[2], aKlo[2], aVhi[2], aVlo[2];
    #pragma unroll
    for (int bf = 0; bf < 2; bf++) {
        aKhi[bf] = smem_u32(&sKhi[bf][k_key * KST + k_c8]);
        aKlo[bf] = smem_u32(&sKlo[bf][k_key * KST + k_c8]);
        aVhi[bf] = smem_u32(&sVhi[bf][v_d * VST + v_kc]);
        aVlo[bf] = smem_u32(&sVlo[bf][v_d * VST + v_kc]);
    }

    uint32_t qh[4][4], ql[4][4];
    {
        size_t r0 = (size_t)(b * SEQ_LEN + q0 + wm + er) * EMBED_DIM + h * HEAD_DIM;
        size_t r1 = r0 + 8 * EMBED_DIM;
        #pragma unroll
        for (int c = 0; c < 4; c++) {
            int cc = c * 16 + ec;
            qh[c][0] = *(const uint32_t*)&g_Qhi[r0 + cc];
            qh[c][1] = *(const uint32_t*)&g_Qhi[r1 + cc];
            qh[c][2] = *(const uint32_t*)&g_Qhi[r0 + cc + 8];
            qh[c][3] = *(const uint32_t*)&g_Qhi[r1 + cc + 8];
            ql[c][0] = *(const uint32_t*)&g_Qlo[r0 + cc];
            ql[c][1] = *(const uint32_t*)&g_Qlo[r1 + cc];
            ql[c][2] = *(const uint32_t*)&g_Qlo[r0 + cc + 8];
            ql[c][3] = *(const uint32_t*)&g_Qlo[r1 + cc + 8];
        }
    }

    float m0r = -1e30f, m1r = -1e30f, l0 = 0.f, l1 = 0.f;
    float o[8][4];
    #pragma unroll
    for (int ni = 0; ni < 8; ni++)
        #pragma unroll
        for (int r = 0; r < 4; r++) o[ni][r] = 0.f;

    {
        CPA16(aKhi[0], (const void*)&g_Khi[kbase]);
        CPA16(aKlo[0], (const void*)&g_Klo[kbase]);
        CPA16(aVhi[0], (const void*)&g_Vthi[vbase]);
        CPA16(aVlo[0], (const void*)&g_Vtlo[vbase]);
        CPA_COMMIT();
        if (tid < KT)
            mk[0][tid] = (mask[b * SEQ_LEN + tid] == 0) ? -1e20f : 0.f;
        CPA_WAIT0();
    }
    __syncthreads();

    for (int ti = 0; ti < NT; ti++) {
        const int cur = ti & 1;
        const int nb  = cur ^ 1;
        const bool nx = (ti + 1) < NT;

        int nmv = 1;
        if (nx) {
            size_t kg = kbase + (size_t)(ti + 1) * KT * EMBED_DIM;
            size_t vg = vbase + (size_t)(ti + 1) * KT;
            CPA16(aKhi[nb], (const void*)&g_Khi[kg]);
            CPA16(aKlo[nb], (const void*)&g_Klo[kg]);
            CPA16(aVhi[nb], (const void*)&g_Vthi[vg]);
            CPA16(aVlo[nb], (const void*)&g_Vtlo[vg]);
            CPA_COMMIT();
            if (tid < KT) nmv = mask[b * SEQ_LEN + (ti + 1) * KT + tid];
        }

        float s[4][4];
        #pragma unroll
        for (int j = 0; j < 4; j++)
            #pragma unroll
            for (int r = 0; r < 4; r++) s[j][r] = 0.f;
        #pragma unroll
        for (int c = 0; c < 4; c++) {
            uint32_t bb[4][2];
            #pragma unroll
            for (int np = 0; np < 2; np++) {
                uint32_t ad = smem_u32(&sKhi[cur][(np * 16 + b_r) * KST + c * 16 + b_c8]);
                ldm_x4(bb[2*np][0], bb[2*np][1], bb[2*np+1][0], bb[2*np+1][1], ad);
            }
            #pragma unroll
            for (int j = 0; j < 4; j++) mma16816(s[j], qh[c], bb[j]);
            #pragma unroll
            for (int j = 0; j < 4; j++) mma16816(s[j], ql[c], bb[j]);
            #pragma unroll
            for (int np = 0; np < 2; np++) {
                uint32_t ad = smem_u32(&sKlo[cur][(np * 16 + b_r) * KST + c * 16 + b_c8]);
                ldm_x4(bb[2*np][0], bb[2*np][1], bb[2*np+1][0], bb[2*np+1][1], ad);
            }
            #pragma unroll
            for (int j = 0; j < 4; j++) mma16816(s[j], qh[c], bb[j]);
        }

        #pragma unroll
        for (int j = 0; j < 4; j++) {
            float a0 = mk[cur][j * 8 + ec], a1 = mk[cur][j * 8 + ec + 1];
            s[j][0] += a0; s[j][1] += a1; s[j][2] += a0; s[j][3] += a1;
        }
        float r0 = fmaxf(fmaxf(s[0][0], s[0][1]), fmaxf(s[1][0], s[1][1]));
        r0 = fmaxf(r0, fmaxf(fmaxf(s[2][0], s[2][1]), fmaxf(s[3][0], s[3][1])));
        float r1 = fmaxf(fmaxf(s[0][2], s[0][3]), fmaxf(s[1][2], s[1][3]));
        r1 = fmaxf(r1, fmaxf(fmaxf(s[2][2], s[2][3]), fmaxf(s[3][2], s[3][3])));
        r0 = fmaxf(r0, __shfl_xor_sync(0xffffffffu, r0, 1));
        r0 = fmaxf(r0, __shfl_xor_sync(0xffffffffu, r0, 2));
        r1 = fmaxf(r1, __shfl_xor_sync(0xffffffffu, r1, 1));
        r1 = fmaxf(r1, __shfl_xor_sync(0xffffffffu, r1, 2));
        float mn0 = fmaxf(m0r, r0), mn1 = fmaxf(m1r, r1);
        float al0 = __expf(m0r - mn0), al1 = __expf(m1r - mn1);
        m0r = mn0; m1r = mn1;

        float p[4][4], sum0 = 0.f, sum1 = 0.f;
        #pragma unroll
        for (int j = 0; j < 4; j++) {
            p[j][0] = __expf(s[j][0] - mn0); p[j][1] = __expf(s[j][1] - mn0);
            p[j][2] = __expf(s[j][2] - mn1); p[j][3] = __expf(s[j][3] - mn1);
            sum0 += p[j][0] + p[j][1];
            sum1 += p[j][2] + p[j][3];
        }
        sum0 += __shfl_xor_sync(0xffffffffu, sum0, 1);
        sum0 += __shfl_xor_sync(0xffffffffu, sum0, 2);
        sum1 += __shfl_xor_sync(0xffffffffu, sum1, 1);
        sum1 += __shfl_xor_sync(0xffffffffu, sum1, 2);
        l0 = l0 * al0 + sum0;
        l1 = l1 * al1 + sum1;
        // warp-uniform skip: alpha==1.0f exactly when max unchanged -> x1.0 is
        // IEEE identity -> skipping is bit-identical.
        if (!__all_sync(0xffffffffu, (al0 == 1.0f) && (al1 == 1.0f))) {
            #pragma unroll
            for (int ni = 0; ni < 8; ni++) {
                o[ni][0] *= al0; o[ni][1] *= al0; o[ni][2] *= al1; o[ni][3] *= al1;
            }
        }

        uint32_t ph[2][4], pl[2][4];
        #pragma unroll
        for (int c = 0; c < 2; c++) {
            int j0 = 2 * c, j1 = 2 * c + 1;
            split2(p[j0][0], p[j0][1], ph[c][0], pl[c][0]);
            split2(p[j0][2], p[j0][3], ph[c][1], pl[c][1]);
            split2(p[j1][0], p[j1][1], ph[c][2], pl[c][2]);
            split2(p[j1][2], p[j1][3], ph[c][3], pl[c][3]);
        }

        #pragma unroll
        for (int c = 0; c < 2; c++) {
            uint32_t vb[8][2];
            #pragma unroll
            for (int np = 0; np < 4; np++) {
                uint32_t ad = smem_u32(&sVhi[cur][(np * 16 + b_r) * VST + c * 16 + b_c8]);
                ldm_x4(vb[2*np][0], vb[2*np][1], vb[2*np+1][0], vb[2*np+1][1], ad);
            }
            #pragma unroll
            for (int ni = 0; ni < 8; ni++) mma16816(o[ni], ph[c], vb[ni]);
            #pragma unroll
            for (int ni = 0; ni < 8; ni++) mma16816(o[ni], pl[c], vb[ni]);
            #pragma unroll
            for (int np = 0; np < 4; np++) {
                uint32_t ad = smem_u32(&sVlo[cur][(np * 16 + b_r) * VST + c * 16 + b_c8]);
                ldm_x4(vb[2*np][0], vb[2*np][1], vb[2*np+1][0], vb[2*np+1][1], ad);
            }
            #pragma unroll
            for (int ni = 0; ni < 8; ni++) mma16816(o[ni], ph[c], vb[ni]);
        }

        if (nx) {
            CPA_WAIT0();
            if (tid < KT) mk[nb][tid] = (nmv == 0) ? -1e20f : 0.f;
        }
        __syncthreads();
    }

    {
        float i0 = 1.f / l0, i1 = 1.f / l1;
        size_t r0o = (size_t)(b * SEQ_LEN + q0 + wm + er) * EMBED_DIM + h * HEAD_DIM;
        size_t r1o = r0o + 8 * EMBED_DIM;
        #pragma unroll
        for (int ni = 0; ni < 8; ni++) {
            int d = ni * 8 + ec;
            uint32_t hh, ll;
            split2(o[ni][0] * i0, o[ni][1] * i0, hh, ll);
            *(uint32_t*)&g_Ahi[r0o + d] = hh;
            *(uint32_t*)&g_Alo[r0o + d] = ll;
            split2(o[ni][2] * i1, o[ni][3] * i1, hh, ll);
            *(uint32_t*)&g_Ahi[r1o + d] = hh;
            *(uint32_t*)&g_Alo[r1o + d] = ll;
        }
    }
}

// =================================================================================
// kernel_launch: FOUR launches, no runtime API calls.
// =================================================================================
extern "C" void kernel_launch(void* const* d_in, const int* in_sizes, int n_in,
                              void* d_out, int out_size)
{
    const float* values = (const float*)d_in[0];
    const float* keys   = (const float*)d_in[1];
    const float* query  = (const float*)d_in[2];
    const int*   mask   = (const int*)  d_in[3];
    const float* W_q    = (const float*)d_in[4];
    const float* W_k    = (const float*)d_in[5];
    const float* W_v    = (const float*)d_in[6];
    const float* W_o    = (const float*)d_in[7];
    const float* b_o    = (const float*)d_in[8];
    float* out = (float*)d_out;

    // split all 4 weight matrices once (4 x 2^18 float4 chunks)
    wsplit_kernel<<<4096, 256>>>(W_q, W_k, W_v, W_o);

    dim3 qkv_grid(EMBED_DIM / GBN, NTOK / GBM, 3);      // (8, 32, 3) = 768 CTAs
    gemm_mma_kernel<<<qkv_grid, 256>>>(query, keys, values,
                                       nullptr, -1, 0, nullptr);

    dim3 agrid(SEQ_LEN / QT, 2 * 16);                   // 512 CTAs
    attn_kernel<<<agrid, 256>>>(mask);

    dim3 ogrid(EMBED_DIM / GBN, NTOK / GBM);            // 256 CTAs
    gemm_mma_kernel<<<ogrid, 256>>>(nullptr, nullptr, nullptr,
                                    b_o, OUT_EXT, 3, out);
}

// round 16
// speedup vs baseline: 1.1773x; 1.1773x over previous
#include <cuda_runtime.h>
#include <cuda_bf16.h>
#include <cstdint>

// Problem constants: N=2, L=2048, EMBED=1024, HEADS=16, Dh=64
#define SEQ_LEN   2048
#define EMBED_DIM 1024
#define NTOK      4096
#define HEAD_DIM  64

// ---------------- warp-MMA helpers (verified R8-R14) ----------------
__device__ __forceinline__ uint32_t smem_u32(const void* p) {
    uint32_t a;
    asm("{ .reg .u64 t; cvta.to.shared.u64 t, %1; cvt.u32.u64 %0, t; }"
        : "=r"(a) : "l"(p));
    return a;
}
__device__ __forceinline__ void ldm_x4(uint32_t& r0, uint32_t& r1,
                                       uint32_t& r2, uint32_t& r3, uint32_t addr) {
    asm volatile("ldmatrix.sync.aligned.m8n8.x4.shared.b16 {%0,%1,%2,%3}, [%4];"
                 : "=r"(r0), "=r"(r1), "=r"(r2), "=r"(r3) : "r"(addr));
}
__device__ __forceinline__ void mma16816(float* c, const uint32_t* a, const uint32_t* b) {
    asm volatile(
        "mma.sync.aligned.m16n8k16.row.col.f32.bf16.bf16.f32 "
        "{%0,%1,%2,%3}, {%4,%5,%6,%7}, {%8,%9}, {%0,%1,%2,%3};"
        : "+f"(c[0]), "+f"(c[1]), "+f"(c[2]), "+f"(c[3])
        : "r"(a[0]), "r"(a[1]), "r"(a[2]), "r"(a[3]), "r"(b[0]), "r"(b[1]));
}
__device__ __forceinline__ void split2(float a, float b, uint32_t& h, uint32_t& l) {
    __nv_bfloat16 ha = __float2bfloat16(a), hb = __float2bfloat16(b);
    __nv_bfloat16 la = __float2bfloat16(a - __bfloat162float(ha));
    __nv_bfloat16 lb = __float2bfloat16(b - __bfloat162float(hb));
    h = (uint32_t)__bfloat16_as_ushort(ha) | ((uint32_t)__bfloat16_as_ushort(hb) << 16);
    l = (uint32_t)__bfloat16_as_ushort(la) | ((uint32_t)__bfloat16_as_ushort(lb) << 16);
}

// cp.async (sm_80 baseline PTX)
#define CPA16(sa, ga) \
    asm volatile("cp.async.cg.shared.global [%0], [%1], 16;" :: "r"(sa), "l"(ga))
#define CPA_COMMIT() asm volatile("cp.async.commit_group;" ::: "memory")
#define CPA_WAIT0()  asm volatile("cp.async.wait_group 0;" ::: "memory")

// ---------------- scratch (device globals: allocation-guard safe) ----------------
__device__ __nv_bfloat16 g_Ahi [NTOK * EMBED_DIM];   // attn output -> final GEMM A
__device__ __nv_bfloat16 g_Alo [NTOK * EMBED_DIM];
__device__ __nv_bfloat16 g_Qhi [NTOK * EMBED_DIM];   // pre-scaled by 0.125
__device__ __nv_bfloat16 g_Qlo [NTOK * EMBED_DIM];
__device__ __nv_bfloat16 g_Khi [NTOK * EMBED_DIM];
__device__ __nv_bfloat16 g_Klo [NTOK * EMBED_DIM];
__device__ __nv_bfloat16 g_Vthi[NTOK * EMBED_DIM];   // [bh][d][token]
__device__ __nv_bfloat16 g_Vtlo[NTOK * EMBED_DIM];
// pre-split weights: index 0=W_q, 1=W_k, 2=W_v, 3=W_o
__device__ __nv_bfloat16 g_Whi [4][EMBED_DIM * EMBED_DIM];
__device__ __nv_bfloat16 g_Wlo [4][EMBED_DIM * EMBED_DIM];

#define OUT_Q   0
#define OUT_K   1
#define OUT_V   2
#define OUT_EXT 4

// =================================================================================
// wsplit_kernel: split ALL FOUR weight matrices fp32 -> bf16 hi/lo in one launch.
// Same split2 values as R14's in-staging conversion -> GEMM inputs bit-identical.
// =================================================================================
__global__ void __launch_bounds__(256) wsplit_kernel(
    const float* __restrict__ w0, const float* __restrict__ w1,
    const float* __restrict__ w2, const float* __restrict__ w3)
{
    int i = blockIdx.x * 256 + threadIdx.x;   // float4 index over 4 matrices
    int m = i >> 18;                          // 2^18 float4 per 1024x1024 matrix
    int j = i & 0x3FFFF;
    const float* w = (m == 0) ? w0 : (m == 1) ? w1 : (m == 2) ? w2 : w3;
    float4 v = ((const float4*)w)[j];
    uint2 H, L;
    split2(v.x, v.y, H.x, L.x);
    split2(v.z, v.w, H.y, L.y);
    ((uint2*)g_Whi[m])[j] = H;
    ((uint2*)g_Wlo[m])[j] = L;
}

// staged pair: either (hi uint4, lo uint4) [bf16 path] or 8 raw fp32 [fp32 path]
struct U4x2 { uint4 a, b; };

// A operand: f32p != null -> 8 fp32; else 8+8 bf16 from g_Ahi/g_Alo
__device__ __forceinline__ U4x2 ld_a(const float* f32p, int row, int col_e) {
    U4x2 r;
    if (f32p) {
        const uint4* p = (const uint4*)&f32p[(size_t)row * EMBED_DIM + col_e];
        r.a = p[0]; r.b = p[1];
    } else {
        size_t o = (size_t)row * EMBED_DIM + col_e;
        r.a = *(const uint4*)&g_Ahi[o];
        r.b = *(const uint4*)&g_Alo[o];
    }
    return r;
}
__device__ __forceinline__ void st_opnd(__nv_bfloat16* shi, __nv_bfloat16* slo,
                                        uint32_t so, const U4x2& v, bool is_f32) {
    if (is_f32) {
        const float* f = (const float*)&v;
        uint4 H, L;
        split2(f[0], f[1], H.x, L.x); split2(f[2], f[3], H.y, L.y);
        split2(f[4], f[5], H.z, L.z); split2(f[6], f[7], H.w, L.w);
        *(uint4*)&shi[so] = H; *(uint4*)&slo[so] = L;
    } else {
        *(uint4*)&shi[so] = v.a; *(uint4*)&slo[so] = v.b;
    }
}

// =================================================================================
// Tensor-core GEMM — EXACT R14 loop structure (the R15 "compute reorder" raised
// regs 128->142 and dropped tensor 46.5->36.3%; reverted). Single change vs R14:
// W read from PRE-SPLIT bf16 (halved W LDG bytes, no W conversion ALU in staging).
//   STS(t+1 -> free buf) -> LDG(t+2 -> regs) -> compute(t) -> ONE syncthreads.
// Accumulation order identical to R14 -> rel_err bit-identical (2.173874e-05).
// =================================================================================
#define GBM 128
#define GBN 128
#define GKC 16
#define GST 24                    // bf16 per smem row (16 data + 8 pad)
#define GNB (EMBED_DIM / GKC)     // 64 k-blocks

__global__ void __launch_bounds__(256) gemm_mma_kernel(
    const float* __restrict__ A0, const float* __restrict__ A1, const float* __restrict__ A2,
    const float* __restrict__ bias, int out_sel_p, int wsel_p, float* ext_out)
{
    int out_sel, wsel;
    const float* Af;
    if (out_sel_p < 0) {                      // batched QKV: z = 0/1/2
        out_sel = blockIdx.z;
        wsel    = blockIdx.z;
        Af = (blockIdx.z == 0) ? A0 : (blockIdx.z == 1) ? A1 : A2;
    } else {
        out_sel = out_sel_p;
        wsel    = wsel_p;
        Af = A0;                              // null -> bf16 path (g_Ahi/g_Alo)
    }
    const bool a_f32 = (Af != nullptr);
    const __nv_bfloat16* __restrict__ Whi = g_Whi[wsel];
    const __nv_bfloat16* __restrict__ Wlo = g_Wlo[wsel];

    // 2-stage buffers: 4 arrays x 2 x 128 x 24 x 2B = 49152 B = 48KB exactly
    __shared__ __align__(16) __nv_bfloat16 sAhi[2][GBM * GST];
    __shared__ __align__(16) __nv_bfloat16 sAlo[2][GBM * GST];
    __shared__ __align__(16) __nv_bfloat16 sBhi[2][GBN * GST];
    __shared__ __align__(16) __nv_bfloat16 sBlo[2][GBN * GST];

    const int tid  = threadIdx.x;
    const int lane = tid & 31;
    const int wid  = tid >> 5;
    const int wm0  = (wid & 3) * 32;
    const int wn0  = (wid >> 2) * 64;
    const int m0   = blockIdx.y * GBM;
    const int n0   = blockIdx.x * GBN;

    const int a_r  = lane & 15;
    const int a_c8 = (lane >> 4) << 3;
    const int b_r  = (lane & 7) + (((lane >> 4) & 1) << 3);
    const int b_c8 = ((lane >> 3) & 1) << 3;

    float acc[2][8][4];
    #pragma unroll
    for (int mi = 0; mi < 2; mi++)
        #pragma unroll
        for (int ni = 0; ni < 8; ni++)
            #pragma unroll
            for (int r = 0; r < 4; r++) acc[mi][ni][r] = 0.f;

    // staging: 128 rows x 2 chunks per operand; each thread does 1 A + 1 B chunk
    const int sr  = tid >> 1;                 // row 0..127
    const int sck = (tid & 1) * 8;            // k chunk 0 or 8
    const uint32_t so = (uint32_t)(sr * GST + sck);
    const size_t wrow = (size_t)(n0 + sr) * EMBED_DIM;

    // pipeline preamble: stage block 0, then load block 1 into regs
    U4x2 rA = ld_a(Af, m0 + sr, sck);
    U4x2 rB;
    rB.a = *(const uint4*)&Whi[wrow + sck];
    rB.b = *(const uint4*)&Wlo[wrow + sck];
    st_opnd(sAhi[0], sAlo[0], so, rA, a_f32);
    st_opnd(sBhi[0], sBlo[0], so, rB, false);
    rA = ld_a(Af, m0 + sr, GKC + sck);
    rB.a = *(const uint4*)&Whi[wrow + GKC + sck];
    rB.b = *(const uint4*)&Wlo[wrow + GKC + sck];
    __syncthreads();

    for (int t = 0; t < GNB; t++) {
        const int cur = t & 1;
        const int nb  = cur ^ 1;

        // ---- stage t+1 into the free buffer (regs hold it); overlaps compute stalls
        if (t + 1 < GNB) {
            st_opnd(sAhi[nb], sAlo[nb], so, rA, a_f32);
            st_opnd(sBhi[nb], sBlo[nb], so, rB, false);
        }
        // ---- LDG t+2 into regs (latency covered by compute below)
        if (t + 2 < GNB) {
            int kc = (t + 2) * GKC + sck;
            rA = ld_a(Af, m0 + sr, kc);
            rB.a = *(const uint4*)&Whi[wrow + kc];
            rB.b = *(const uint4*)&Wlo[wrow + kc];
        }

        // ---- compute block t (R14 order: ldmatrix inside; products hihi, lohi, hilo)
        {
            uint32_t ah[2][4], al[2][4], bb[8][2];
            #pragma unroll
            for (int mi = 0; mi < 2; mi++) {
                uint32_t ad = smem_u32(&sAhi[cur][(wm0 + mi * 16 + a_r) * GST + a_c8]);
                ldm_x4(ah[mi][0], ah[mi][1], ah[mi][2], ah[mi][3], ad);
                ad = smem_u32(&sAlo[cur][(wm0 + mi * 16 + a_r) * GST + a_c8]);
                ldm_x4(al[mi][0], al[mi][1], al[mi][2], al[mi][3], ad);
            }
            #pragma unroll
            for (int np = 0; np < 4; np++) {
                uint32_t ad = smem_u32(&sBhi[cur][(wn0 + np * 16 + b_r) * GST + b_c8]);
                ldm_x4(bb[2 * np][0], bb[2 * np][1], bb[2 * np + 1][0], bb[2 * np + 1][1], ad);
            }
            #pragma unroll
            for (int mi = 0; mi < 2; mi++)
                #pragma unroll
                for (int ni = 0; ni < 8; ni++) mma16816(acc[mi][ni], ah[mi], bb[ni]);
            #pragma unroll
            for (int mi = 0; mi < 2; mi++)
                #pragma unroll
                for (int ni = 0; ni < 8; ni++) mma16816(acc[mi][ni], al[mi], bb[ni]);
            #pragma unroll
            for (int np = 0; np < 4; np++) {
                uint32_t ad = smem_u32(&sBlo[cur][(wn0 + np * 16 + b_r) * GST + b_c8]);
                ldm_x4(bb[2 * np][0], bb[2 * np][1], bb[2 * np + 1][0], bb[2 * np + 1][1], ad);
            }
            #pragma unroll
            for (int mi = 0; mi < 2; mi++)
                #pragma unroll
                for (int ni = 0; ni < 8; ni++) mma16816(acc[mi][ni], ah[mi], bb[ni]);
        }
        __syncthreads();   // gates: readers of cur done AND writers of nb done
    }

    const int er = lane >> 2;
    const int ec = (lane & 3) * 2;
    #pragma unroll
    for (int mi = 0; mi < 2; mi++) {
        #pragma unroll
        for (int ni = 0; ni < 8; ni++) {
            int row = m0 + wm0 + mi * 16 + er;
            int col = n0 + wn0 + ni * 8 + ec;
            float v00 = acc[mi][ni][0], v01 = acc[mi][ni][1];
            float v10 = acc[mi][ni][2], v11 = acc[mi][ni][3];
            if (out_sel == OUT_EXT) {
                float b0 = bias ? bias[col] : 0.f, b1 = bias ? bias[col + 1] : 0.f;
                *(float2*)&ext_out[(size_t)row * EMBED_DIM + col] = make_float2(v00 + b0, v01 + b1);
                *(float2*)&ext_out[(size_t)(row + 8) * EMBED_DIM + col] = make_float2(v10 + b0, v11 + b1);
            } else if (out_sel == OUT_V) {
                int bb_ = row >> 11, tok = row & 2047;
                int hh  = col >> 6,  dd  = col & 63;
                size_t base = ((size_t)(bb_ * 16 + hh) * 64 + dd) * SEQ_LEN + tok;
                uint32_t h0, l0, h1, l1;
                split2(v00, v10, h0, l0);
                split2(v01, v11, h1, l1);
                g_Vthi[base]               = __ushort_as_bfloat16((unsigned short)(h0 & 0xffff));
                g_Vthi[base + 8]           = __ushort_as_bfloat16((unsigned short)(h0 >> 16));
                g_Vtlo[base]               = __ushort_as_bfloat16((unsigned short)(l0 & 0xffff));
                g_Vtlo[base + 8]           = __ushort_as_bfloat16((unsigned short)(l0 >> 16));
                g_Vthi[base + SEQ_LEN]     = __ushort_as_bfloat16((unsigned short)(h1 & 0xffff));
                g_Vthi[base + SEQ_LEN + 8] = __ushort_as_bfloat16((unsigned short)(h1 >> 16));
                g_Vtlo[base + SEQ_LEN]     = __ushort_as_bfloat16((unsigned short)(l1 & 0xffff));
                g_Vtlo[base + SEQ_LEN + 8] = __ushort_as_bfloat16((unsigned short)(l1 >> 16));
            } else {
                __nv_bfloat16* hi = (out_sel == OUT_Q) ? g_Qhi : g_Khi;
                __nv_bfloat16* lo = (out_sel == OUT_Q) ? g_Qlo : g_Klo;
                float sc = (out_sel == OUT_Q) ? 0.125f : 1.f;
                uint32_t h, l;
                split2(v00 * sc, v01 * sc, h, l);
                *(uint32_t*)&hi[(size_t)row * EMBED_DIM + col] = h;
                *(uint32_t*)&lo[(size_t)row * EMBED_DIM + col] = l;
                split2(v10 * sc, v11 * sc, h, l);
                *(uint32_t*)&hi[(size_t)(row + 8) * EMBED_DIM + col] = h;
                *(uint32_t*)&lo[(size_t)(row + 8) * EMBED_DIM + col] = l;
            }
        }
    }
}

// =================================================================================
// Tensor-core flash attention — EXACT R14 (R15's rescale skip also reverted to
// keep this round a single-variable experiment).
// =================================================================================
#define QT 128
#define KT 32
#define KST 72
#define VST 40
#define NT (SEQ_LEN / KT)

__global__ void __launch_bounds__(256) attn_kernel(const int* __restrict__ mask)
{
    __shared__ __align__(16) __nv_bfloat16 sKhi[2][KT * KST];
    __shared__ __align__(16) __nv_bfloat16 sKlo[2][KT * KST];
    __shared__ __align__(16) __nv_bfloat16 sVhi[2][64 * VST];
    __shared__ __align__(16) __nv_bfloat16 sVlo[2][64 * VST];
    __shared__ float mk[2][KT];

    const int tid  = threadIdx.x;
    const int lane = tid & 31;
    const int wid  = tid >> 5;
    const int wm   = wid * 16;
    const int q0   = blockIdx.x * QT;
    const int b    = blockIdx.y >> 4;
    const int h    = blockIdx.y & 15;

    const int er   = lane >> 2;
    const int ec   = (lane & 3) * 2;
    const int b_r  = (lane & 7) + (((lane >> 4) & 1) << 3);
    const int b_c8 = ((lane >> 3) & 1) << 3;

    const int k_key = tid >> 3, k_c8 = (tid & 7) * 8;
    const int v_d   = tid >> 2, v_kc = (tid & 3) * 8;
    const size_t kbase = (size_t)(b * SEQ_LEN + k_key) * EMBED_DIM + h * HEAD_DIM + k_c8;
    const size_t vbase = ((size_t)(b * 16 + h) * HEAD_DIM + v_d) * SEQ_LEN + v_kc;
    uint32_t aKhi[2], aKlo[2], aVhi[2], aVlo[2];
    #pragma unroll
    for (int bf = 0; bf < 2; bf++) {
        aKhi[bf] = smem_u32(&sKhi[bf][k_key * KST + k_c8]);
        aKlo[bf] = smem_u32(&sKlo[bf][k_key * KST + k_c8]);
        aVhi[bf] = smem_u32(&sVhi[bf][v_d * VST + v_kc]);
        aVlo[bf] = smem_u32(&sVlo[bf][v_d * VST + v_kc]);
    }

    uint32_t qh[4][4], ql[4][4];
    {
        size_t r0 = (size_t)(b * SEQ_LEN + q0 + wm + er) * EMBED_DIM + h * HEAD_DIM;
        size_t r1 = r0 + 8 * EMBED_DIM;
        #pragma unroll
        for (int c = 0; c < 4; c++) {
            int cc = c * 16 + ec;
            qh[c][0] = *(const uint32_t*)&g_Qhi[r0 + cc];
            qh[c][1] = *(const uint32_t*)&g_Qhi[r1 + cc];
            qh[c][2] = *(const uint32_t*)&g_Qhi[r0 + cc + 8];
            qh[c][3] = *(const uint32_t*)&g_Qhi[r1 + cc + 8];
            ql[c][0] = *(const uint32_t*)&g_Qlo[r0 + cc];
            ql[c][1] = *(const uint32_t*)&g_Qlo[r1 + cc];
            ql[c][2] = *(const uint32_t*)&g_Qlo[r0 + cc + 8];
            ql[c][3] = *(const uint32_t*)&g_Qlo[r1 + cc + 8];
        }
    }

    float m0r = -1e30f, m1r = -1e30f, l0 = 0.f, l1 = 0.f;
    float o[8][4];
    #pragma unroll
    for (int ni = 0; ni < 8; ni++)
        #pragma unroll
        for (int r = 0; r < 4; r++) o[ni][r] = 0.f;

    {
        CPA16(aKhi[0], (const void*)&g_Khi[kbase]);
        CPA16(aKlo[0], (const void*)&g_Klo[kbase]);
        CPA16(aVhi[0], (const void*)&g_Vthi[vbase]);
        CPA16(aVlo[0], (const void*)&g_Vtlo[vbase]);
        CPA_COMMIT();
        if (tid < KT)
            mk[0][tid] = (mask[b * SEQ_LEN + tid] == 0) ? -1e20f : 0.f;
        CPA_WAIT0();
    }
    __syncthreads();

    for (int ti = 0; ti < NT; ti++) {
        const int cur = ti & 1;
        const int nb  = cur ^ 1;
        const bool nx = (ti + 1) < NT;

        int nmv = 1;
        if (nx) {
            size_t kg = kbase + (size_t)(ti + 1) * KT * EMBED_DIM;
            size_t vg = vbase + (size_t)(ti + 1) * KT;
            CPA16(aKhi[nb], (const void*)&g_Khi[kg]);
            CPA16(aKlo[nb], (const void*)&g_Klo[kg]);
            CPA16(aVhi[nb], (const void*)&g_Vthi[vg]);
            CPA16(aVlo[nb], (const void*)&g_Vtlo[vg]);
            CPA_COMMIT();
            if (tid < KT) nmv = mask[b * SEQ_LEN + (ti + 1) * KT + tid];
        }

        float s[4][4];
        #pragma unroll
        for (int j = 0; j < 4; j++)
            #pragma unroll
            for (int r = 0; r < 4; r++) s[j][r] = 0.f;
        #pragma unroll
        for (int c = 0; c < 4; c++) {
            uint32_t bb[4][2];
            #pragma unroll
            for (int np = 0; np < 2; np++) {
                uint32_t ad = smem_u32(&sKhi[cur][(np * 16 + b_r) * KST + c * 16 + b_c8]);
                ldm_x4(bb[2*np][0], bb[2*np][1], bb[2*np+1][0], bb[2*np+1][1], ad);
            }
            #pragma unroll
            for (int j = 0; j < 4; j++) mma16816(s[j], qh[c], bb[j]);
            #pragma unroll
            for (int j = 0; j < 4; j++) mma16816(s[j], ql[c], bb[j]);
            #pragma unroll
            for (int np = 0; np < 2; np++) {
                uint32_t ad = smem_u32(&sKlo[cur][(np * 16 + b_r) * KST + c * 16 + b_c8]);
                ldm_x4(bb[2*np][0], bb[2*np][1], bb[2*np+1][0], bb[2*np+1][1], ad);
            }
            #pragma unroll
            for (int j = 0; j < 4; j++) mma16816(s[j], qh[c], bb[j]);
        }

        #pragma unroll
        for (int j = 0; j < 4; j++) {
            float a0 = mk[cur][j * 8 + ec], a1 = mk[cur][j * 8 + ec + 1];
            s[j][0] += a0; s[j][1] += a1; s[j][2] += a0; s[j][3] += a1;
        }
        float r0 = fmaxf(fmaxf(s[0][0], s[0][1]), fmaxf(s[1][0], s[1][1]));
        r0 = fmaxf(r0, fmaxf(fmaxf(s[2][0], s[2][1]), fmaxf(s[3][0], s[3][1])));
        float r1 = fmaxf(fmaxf(s[0][2], s[0][3]), fmaxf(s[1][2], s[1][3]));
        r1 = fmaxf(r1, fmaxf(fmaxf(s[2][2], s[2][3]), fmaxf(s[3][2], s[3][3])));
        r0 = fmaxf(r0, __shfl_xor_sync(0xffffffffu, r0, 1));
        r0 = fmaxf(r0, __shfl_xor_sync(0xffffffffu, r0, 2));
        r1 = fmaxf(r1, __shfl_xor_sync(0xffffffffu, r1, 1));
        r1 = fmaxf(r1, __shfl_xor_sync(0xffffffffu, r1, 2));
        float mn0 = fmaxf(m0r, r0), mn1 = fmaxf(m1r, r1);
        float al0 = __expf(m0r - mn0), al1 = __expf(m1r - mn1);
        m0r = mn0; m1r = mn1;

        float p[4][4], sum0 = 0.f, sum1 = 0.f;
        #pragma unroll
        for (int j = 0; j < 4; j++) {
            p[j][0] = __expf(s[j][0] - mn0); p[j][1] = __expf(s[j][1] - mn0);
            p[j][2] = __expf(s[j][2] - mn1); p[j][3] = __expf(s[j][3] - mn1);
            sum0 += p[j][0] + p[j][1];
            sum1 += p[j][2] + p[j][3];
        }
        sum0 += __shfl_xor_sync(0xffffffffu, sum0, 1);
        sum0 += __shfl_xor_sync(0xffffffffu, sum0, 2);
        sum1 += __shfl_xor_sync(0xffffffffu, sum1, 1);
        sum1 += __shfl_xor_sync(0xffffffffu, sum1, 2);
        l0 = l0 * al0 + sum0;
        l1 = l1 * al1 + sum1;
        #pragma unroll
        for (int ni = 0; ni < 8; ni++) {
            o[ni][0] *= al0; o[ni][1] *= al0; o[ni][2] *= al1; o[ni][3] *= al1;
        }

        uint32_t ph[2][4], pl[2][4];
        #pragma unroll
        for (int c = 0; c < 2; c++) {
            int j0 = 2 * c, j1 = 2 * c + 1;
            split2(p[j0][0], p[j0][1], ph[c][0], pl[c][0]);
            split2(p[j0][2], p[j0][3], ph[c][1], pl[c][1]);
            split2(p[j1][0], p[j1][1], ph[c][2], pl[c][2]);
            split2(p[j1][2], p[j1][3], ph[c][3], pl[c][3]);
        }

        #pragma unroll
        for (int c = 0; c < 2; c++) {
            uint32_t vb[8][2];
            #pragma unroll
            for (int np = 0; np < 4; np++) {
                uint32_t ad = smem_u32(&sVhi[cur][(np * 16 + b_r) * VST + c * 16 + b_c8]);
                ldm_x4(vb[2*np][0], vb[2*np][1], vb[2*np+1][0], vb[2*np+1][1], ad);
            }
            #pragma unroll
            for (int ni = 0; ni < 8; ni++) mma16816(o[ni], ph[c], vb[ni]);
            #pragma unroll
            for (int ni = 0; ni < 8; ni++) mma16816(o[ni], pl[c], vb[ni]);
            #pragma unroll
            for (int np = 0; np < 4; np++) {
                uint32_t ad = smem_u32(&sVlo[cur][(np * 16 + b_r) * VST + c * 16 + b_c8]);
                ldm_x4(vb[2*np][0], vb[2*np][1], vb[2*np+1][0], vb[2*np+1][1], ad);
            }
            #pragma unroll
            for (int ni = 0; ni < 8; ni++) mma16816(o[ni], ph[c], vb[ni]);
        }

        if (nx) {
            CPA_WAIT0();
            if (tid < KT) mk[nb][tid] = (nmv == 0) ? -1e20f : 0.f;
        }
        __syncthreads();
    }

    {
        float i0 = 1.f / l0, i1 = 1.f / l1;
        size_t r0o = (size_t)(b * SEQ_LEN + q0 + wm + er) * EMBED_DIM + h * HEAD_DIM;
        size_t r1o = r0o + 8 * EMBED_DIM;
        #pragma unroll
        for (int ni = 0; ni < 8; ni++) {
            int d = ni * 8 + ec;
            uint32_t hh, ll;
            split2(o[ni][0] * i0, o[ni][1] * i0, hh, ll);
            *(uint32_t*)&g_Ahi[r0o + d] = hh;
            *(uint32_t*)&g_Alo[r0o + d] = ll;
            split2(o[ni][2] * i1, o[ni][3] * i1, hh, ll);
            *(uint32_t*)&g_Ahi[r1o + d] = hh;
            *(uint32_t*)&g_Alo[r1o + d] = ll;
        }
    }
}

// =================================================================================
// kernel_launch: FOUR launches, no runtime API calls.
// =================================================================================
extern "C" void kernel_launch(void* const* d_in, const int* in_sizes, int n_in,
                              void* d_out, int out_size)
{
    const float* values = (const float*)d_in[0];
    const float* keys   = (const float*)d_in[1];
    const float* query  = (const float*)d_in[2];
    const int*   mask   = (const int*)  d_in[3];
    const float* W_q    = (const float*)d_in[4];
    const float* W_k    = (const float*)d_in[5];
    const float* W_v    = (const float*)d_in[6];
    const float* W_o    = (const float*)d_in[7];
    const float* b_o    = (const float*)d_in[8];
    float* out = (float*)d_out;

    // split all 4 weight matrices once (4 x 2^18 float4 chunks)
    wsplit_kernel<<<4096, 256>>>(W_q, W_k, W_v, W_o);

    dim3 qkv_grid(EMBED_DIM / GBN, NTOK / GBM, 3);      // (8, 32, 3) = 768 CTAs
    gemm_mma_kernel<<<qkv_grid, 256>>>(query, keys, values,
                                       nullptr, -1, 0, nullptr);

    dim3 agrid(SEQ_LEN / QT, 2 * 16);                   // 512 CTAs
    attn_kernel<<<agrid, 256>>>(mask);

    dim3 ogrid(EMBED_DIM / GBN, NTOK / GBM);            // 256 CTAs
    gemm_mma_kernel<<<ogrid, 256>>>(nullptr, nullptr, nullptr,
                                    b_o, OUT_EXT, 3, out);
}

// round 17
// speedup vs baseline: 1.2347x; 1.0487x over previous
#include <cuda_runtime.h>
#include <cuda_bf16.h>
#include <cstdint>

// Problem constants: N=2, L=2048, EMBED=1024, HEADS=16, Dh=64
#define SEQ_LEN   2048
#define EMBED_DIM 1024
#define NTOK      4096
#define HEAD_DIM  64

// ---------------- warp-MMA helpers (verified R8-R16) ----------------
__device__ __forceinline__ uint32_t smem_u32(const void* p) {
    uint32_t a;
    asm("{ .reg .u64 t; cvta.to.shared.u64 t, %1; cvt.u32.u64 %0, t; }"
        : "=r"(a) : "l"(p));
    return a;
}
__device__ __forceinline__ void ldm_x4(uint32_t& r0, uint32_t& r1,
                                       uint32_t& r2, uint32_t& r3, uint32_t addr) {
    asm volatile("ldmatrix.sync.aligned.m8n8.x4.shared.b16 {%0,%1,%2,%3}, [%4];"
                 : "=r"(r0), "=r"(r1), "=r"(r2), "=r"(r3) : "r"(addr));
}
__device__ __forceinline__ void mma16816(float* c, const uint32_t* a, const uint32_t* b) {
    asm volatile(
        "mma.sync.aligned.m16n8k16.row.col.f32.bf16.bf16.f32 "
        "{%0,%1,%2,%3}, {%4,%5,%6,%7}, {%8,%9}, {%0,%1,%2,%3};"
        : "+f"(c[0]), "+f"(c[1]), "+f"(c[2]), "+f"(c[3])
        : "r"(a[0]), "r"(a[1]), "r"(a[2]), "r"(a[3]), "r"(b[0]), "r"(b[1]));
}
__device__ __forceinline__ void split2(float a, float b, uint32_t& h, uint32_t& l) {
    __nv_bfloat16 ha = __float2bfloat16(a), hb = __float2bfloat16(b);
    __nv_bfloat16 la = __float2bfloat16(a - __bfloat162float(ha));
    __nv_bfloat16 lb = __float2bfloat16(b - __bfloat162float(hb));
    h = (uint32_t)__bfloat16_as_ushort(ha) | ((uint32_t)__bfloat16_as_ushort(hb) << 16);
    l = (uint32_t)__bfloat16_as_ushort(la) | ((uint32_t)__bfloat16_as_ushort(lb) << 16);
}

// cp.async (sm_80 baseline PTX)
#define CPA16(sa, ga) \
    asm volatile("cp.async.cg.shared.global [%0], [%1], 16;" :: "r"(sa), "l"(ga))
#define CPA_COMMIT() asm volatile("cp.async.commit_group;" ::: "memory")
#define CPA_WAIT0()  asm volatile("cp.async.wait_group 0;" ::: "memory")

// ---------------- scratch (device globals: allocation-guard safe) ----------------
__device__ __nv_bfloat16 g_Ahi [NTOK * EMBED_DIM];   // attn output -> final GEMM A
__device__ __nv_bfloat16 g_Alo [NTOK * EMBED_DIM];
__device__ __nv_bfloat16 g_Qhi [NTOK * EMBED_DIM];   // pre-scaled by 0.125
__device__ __nv_bfloat16 g_Qlo [NTOK * EMBED_DIM];
__device__ __nv_bfloat16 g_Khi [NTOK * EMBED_DIM];
__device__ __nv_bfloat16 g_Klo [NTOK * EMBED_DIM];
__device__ __nv_bfloat16 g_Vthi[NTOK * EMBED_DIM];   // [bh][d][token]
__device__ __nv_bfloat16 g_Vtlo[NTOK * EMBED_DIM];
// pre-split weights: index 0=W_q, 1=W_k, 2=W_v, 3=W_o
__device__ __nv_bfloat16 g_Whi [4][EMBED_DIM * EMBED_DIM];
__device__ __nv_bfloat16 g_Wlo [4][EMBED_DIM * EMBED_DIM];

#define OUT_Q   0
#define OUT_K   1
#define OUT_V   2
#define OUT_EXT 4

// =================================================================================
// wsplit_kernel: split ALL FOUR weight matrices fp32 -> bf16 hi/lo in one launch.
// =================================================================================
__global__ void __launch_bounds__(256) wsplit_kernel(
    const float* __restrict__ w0, const float* __restrict__ w1,
    const float* __restrict__ w2, const float* __restrict__ w3)
{
    int i = blockIdx.x * 256 + threadIdx.x;   // float4 index over 4 matrices
    int m = i >> 18;                          // 2^18 float4 per 1024x1024 matrix
    int j = i & 0x3FFFF;
    const float* w = (m == 0) ? w0 : (m == 1) ? w1 : (m == 2) ? w2 : w3;
    float4 v = ((const float4*)w)[j];
    uint2 H, L;
    split2(v.x, v.y, H.x, L.x);
    split2(v.z, v.w, H.y, L.y);
    ((uint2*)g_Whi[m])[j] = H;
    ((uint2*)g_Wlo[m])[j] = L;
}

// staged A pair: 8 fp32 in regs (fp32 path only)
struct U4x2 { uint4 a, b; };

__device__ __forceinline__ U4x2 ld_a32(const float* f32p, int row, int col_e) {
    U4x2 r;
    const uint4* p = (const uint4*)&f32p[(size_t)row * EMBED_DIM + col_e];
    r.a = p[0]; r.b = p[1];
    return r;
}
__device__ __forceinline__ void st_a32(__nv_bfloat16* shi, __nv_bfloat16* slo,
                                       uint32_t so, const U4x2& v) {
    const float* f = (const float*)&v;
    uint4 H, L;
    split2(f[0], f[1], H.x, L.x); split2(f[2], f[3], H.y, L.y);
    split2(f[4], f[5], H.z, L.z); split2(f[6], f[7], H.w, L.w);
    *(uint4*)&shi[so] = H; *(uint4*)&slo[so] = L;
}

// =================================================================================
// Tensor-core GEMM — R16 compute core; staging upgraded to cp.async wherever the
// source is bf16 (B/W always; A too on the O-proj path). fp32 A (QKV) keeps the
// reg+STS path. Bytes landing in smem are IDENTICAL -> rel_err bit-identical.
//   [CPA B(t+1) (+ CPA A or STS A)] -> [LDG A(t+2) if fp32] -> compute(t)
//   -> CPA_WAIT -> ONE syncthreads.
// =================================================================================
#define GBM 128
#define GBN 128
#define GKC 16
#define GST 24                    // bf16 per smem row (16 data + 8 pad), 48B stride
#define GNB (EMBED_DIM / GKC)     // 64 k-blocks

__global__ void __launch_bounds__(256) gemm_mma_kernel(
    const float* __restrict__ A0, const float* __restrict__ A1, const float* __restrict__ A2,
    const float* __restrict__ bias, int out_sel_p, int wsel_p, float* ext_out)
{
    int out_sel, wsel;
    const float* Af;
    if (out_sel_p < 0) {                      // batched QKV: z = 0/1/2
        out_sel = blockIdx.z;
        wsel    = blockIdx.z;
        Af = (blockIdx.z == 0) ? A0 : (blockIdx.z == 1) ? A1 : A2;
    } else {
        out_sel = out_sel_p;
        wsel    = wsel_p;
        Af = A0;                              // null -> bf16 A path (g_Ahi/g_Alo)
    }
    const bool a_f32 = (Af != nullptr);
    const __nv_bfloat16* __restrict__ Whi = g_Whi[wsel];
    const __nv_bfloat16* __restrict__ Wlo = g_Wlo[wsel];

    // 2-stage buffers: 4 arrays x 2 x 128 x 24 x 2B = 49152 B = 48KB exactly
    __shared__ __align__(16) __nv_bfloat16 sAhi[2][GBM * GST];
    __shared__ __align__(16) __nv_bfloat16 sAlo[2][GBM * GST];
    __shared__ __align__(16) __nv_bfloat16 sBhi[2][GBN * GST];
    __shared__ __align__(16) __nv_bfloat16 sBlo[2][GBN * GST];

    const int tid  = threadIdx.x;
    const int lane = tid & 31;
    const int wid  = tid >> 5;
    const int wm0  = (wid & 3) * 32;
    const int wn0  = (wid >> 2) * 64;
    const int m0   = blockIdx.y * GBM;
    const int n0   = blockIdx.x * GBN;

    const int a_r  = lane & 15;
    const int a_c8 = (lane >> 4) << 3;
    const int b_r  = (lane & 7) + (((lane >> 4) & 1) << 3);
    const int b_c8 = ((lane >> 3) & 1) << 3;

    float acc[2][8][4];
    #pragma unroll
    for (int mi = 0; mi < 2; mi++)
        #pragma unroll
        for (int ni = 0; ni < 8; ni++)
            #pragma unroll
            for (int r = 0; r < 4; r++) acc[mi][ni][r] = 0.f;

    // staging: 128 rows x 2 chunks per operand; each thread does 1 A + 1 B chunk
    const int sr  = tid >> 1;                 // row 0..127
    const int sck = (tid & 1) * 8;            // k chunk 0 or 8
    const uint32_t so = (uint32_t)(sr * GST + sck);
    const size_t wrow = (size_t)(n0 + sr) * EMBED_DIM;
    const size_t arow = (size_t)(m0 + sr) * EMBED_DIM;

    uint32_t aAhi[2], aAlo[2], aBhi[2], aBlo[2];
    #pragma unroll
    for (int bf = 0; bf < 2; bf++) {
        aAhi[bf] = smem_u32(&sAhi[bf][so]);
        aAlo[bf] = smem_u32(&sAlo[bf][so]);
        aBhi[bf] = smem_u32(&sBhi[bf][so]);
        aBlo[bf] = smem_u32(&sBlo[bf][so]);
    }

    // ---- preamble: stage block 0 (B via cp.async; A via cp.async or regs)
    U4x2 rA;
    CPA16(aBhi[0], (const void*)&Whi[wrow + sck]);
    CPA16(aBlo[0], (const void*)&Wlo[wrow + sck]);
    if (a_f32) {
        rA = ld_a32(Af, m0 + sr, sck);
        st_a32(sAhi[0], sAlo[0], so, rA);
    } else {
        CPA16(aAhi[0], (const void*)&g_Ahi[arow + sck]);
        CPA16(aAlo[0], (const void*)&g_Alo[arow + sck]);
    }
    CPA_COMMIT();
    if (a_f32) rA = ld_a32(Af, m0 + sr, GKC + sck);   // block 1 into regs
    CPA_WAIT0();
    __syncthreads();

    for (int t = 0; t < GNB; t++) {
        const int cur = t & 1;
        const int nb  = cur ^ 1;
        const bool nx = (t + 1) < GNB;

        // ---- issue staging of t+1 into the free buffer
        if (nx) {
            int kc = (t + 1) * GKC + sck;
            CPA16(aBhi[nb], (const void*)&Whi[wrow + kc]);
            CPA16(aBlo[nb], (const void*)&Wlo[wrow + kc]);
            if (a_f32) {
                st_a32(sAhi[nb], sAlo[nb], so, rA);
            } else {
                CPA16(aAhi[nb], (const void*)&g_Ahi[arow + kc]);
                CPA16(aAlo[nb], (const void*)&g_Alo[arow + kc]);
            }
            CPA_COMMIT();
        }
        // ---- LDG A(t+2) into regs (fp32 path only; latency covered by compute)
        if (a_f32 && (t + 2) < GNB)
            rA = ld_a32(Af, m0 + sr, (t + 2) * GKC + sck);

        // ---- compute block t (R14/R16 order; products hihi, lohi, hilo)
        {
            uint32_t ah[2][4], al[2][4], bb[8][2];
            #pragma unroll
            for (int mi = 0; mi < 2; mi++) {
                uint32_t ad = smem_u32(&sAhi[cur][(wm0 + mi * 16 + a_r) * GST + a_c8]);
                ldm_x4(ah[mi][0], ah[mi][1], ah[mi][2], ah[mi][3], ad);
                ad = smem_u32(&sAlo[cur][(wm0 + mi * 16 + a_r) * GST + a_c8]);
                ldm_x4(al[mi][0], al[mi][1], al[mi][2], al[mi][3], ad);
            }
            #pragma unroll
            for (int np = 0; np < 4; np++) {
                uint32_t ad = smem_u32(&sBhi[cur][(wn0 + np * 16 + b_r) * GST + b_c8]);
                ldm_x4(bb[2 * np][0], bb[2 * np][1], bb[2 * np + 1][0], bb[2 * np + 1][1], ad);
            }
            #pragma unroll
            for (int mi = 0; mi < 2; mi++)
                #pragma unroll
                for (int ni = 0; ni < 8; ni++) mma16816(acc[mi][ni], ah[mi], bb[ni]);
            #pragma unroll
            for (int mi = 0; mi < 2; mi++)
                #pragma unroll
                for (int ni = 0; ni < 8; ni++) mma16816(acc[mi][ni], al[mi], bb[ni]);
            #pragma unroll
            for (int np = 0; np < 4; np++) {
                uint32_t ad = smem_u32(&sBlo[cur][(wn0 + np * 16 + b_r) * GST + b_c8]);
                ldm_x4(bb[2 * np][0], bb[2 * np][1], bb[2 * np + 1][0], bb[2 * np + 1][1], ad);
            }
            #pragma unroll
            for (int mi = 0; mi < 2; mi++)
                #pragma unroll
                for (int ni = 0; ni < 8; ni++) mma16816(acc[mi][ni], ah[mi], bb[ni]);
        }

        if (nx) CPA_WAIT0();
        __syncthreads();   // gates: readers of cur done AND writers of nb done
    }

    const int er = lane >> 2;
    const int ec = (lane & 3) * 2;
    #pragma unroll
    for (int mi = 0; mi < 2; mi++) {
        #pragma unroll
        for (int ni = 0; ni < 8; ni++) {
            int row = m0 + wm0 + mi * 16 + er;
            int col = n0 + wn0 + ni * 8 + ec;
            float v00 = acc[mi][ni][0], v01 = acc[mi][ni][1];
            float v10 = acc[mi][ni][2], v11 = acc[mi][ni][3];
            if (out_sel == OUT_EXT) {
                float b0 = bias ? bias[col] : 0.f, b1 = bias ? bias[col + 1] : 0.f;
                *(float2*)&ext_out[(size_t)row * EMBED_DIM + col] = make_float2(v00 + b0, v01 + b1);
                *(float2*)&ext_out[(size_t)(row + 8) * EMBED_DIM + col] = make_float2(v10 + b0, v11 + b1);
            } else if (out_sel == OUT_V) {
                int bb_ = row >> 11, tok = row & 2047;
                int hh  = col >> 6,  dd  = col & 63;
                size_t base = ((size_t)(bb_ * 16 + hh) * 64 + dd) * SEQ_LEN + tok;
                uint32_t h0, l0, h1, l1;
                split2(v00, v10, h0, l0);
                split2(v01, v11, h1, l1);
                g_Vthi[base]               = __ushort_as_bfloat16((unsigned short)(h0 & 0xffff));
                g_Vthi[base + 8]           = __ushort_as_bfloat16((unsigned short)(h0 >> 16));
                g_Vtlo[base]               = __ushort_as_bfloat16((unsigned short)(l0 & 0xffff));
                g_Vtlo[base + 8]           = __ushort_as_bfloat16((unsigned short)(l0 >> 16));
                g_Vthi[base + SEQ_LEN]     = __ushort_as_bfloat16((unsigned short)(h1 & 0xffff));
                g_Vthi[base + SEQ_LEN + 8] = __ushort_as_bfloat16((unsigned short)(h1 >> 16));
                g_Vtlo[base + SEQ_LEN]     = __ushort_as_bfloat16((unsigned short)(l1 & 0xffff));
                g_Vtlo[base + SEQ_LEN + 8] = __ushort_as_bfloat16((unsigned short)(l1 >> 16));
            } else {
                __nv_bfloat16* hi = (out_sel == OUT_Q) ? g_Qhi : g_Khi;
                __nv_bfloat16* lo = (out_sel == OUT_Q) ? g_Qlo : g_Klo;
                float sc = (out_sel == OUT_Q) ? 0.125f : 1.f;
                uint32_t h, l;
                split2(v00 * sc, v01 * sc, h, l);
                *(uint32_t*)&hi[(size_t)row * EMBED_DIM + col] = h;
                *(uint32_t*)&lo[(size_t)row * EMBED_DIM + col] = l;
                split2(v10 * sc, v11 * sc, h, l);
                *(uint32_t*)&hi[(size_t)(row + 8) * EMBED_DIM + col] = h;
                *(uint32_t*)&lo[(size_t)(row + 8) * EMBED_DIM + col] = l;
            }
        }
    }
}

// =================================================================================
// Tensor-core flash attention — R16 + warp-uniform rescale skip (alpha==1.0f
// exactly when the running max is unchanged; x1.0 is IEEE identity on finite
// values, so the skip is BIT-IDENTICAL).
// =================================================================================
#define QT 128
#define KT 32
#define KST 72
#define VST 40
#define NT (SEQ_LEN / KT)

__global__ void __launch_bounds__(256) attn_kernel(const int* __restrict__ mask)
{
    __shared__ __align__(16) __nv_bfloat16 sKhi[2][KT * KST];
    __shared__ __align__(16) __nv_bfloat16 sKlo[2][KT * KST];
    __shared__ __align__(16) __nv_bfloat16 sVhi[2][64 * VST];
    __shared__ __align__(16) __nv_bfloat16 sVlo[2][64 * VST];
    __shared__ float mk[2][KT];

    const int tid  = threadIdx.x;
    const int lane = tid & 31;
    const int wid  = tid >> 5;
    const int wm   = wid * 16;
    const int q0   = blockIdx.x * QT;
    const int b    = blockIdx.y >> 4;
    const int h    = blockIdx.y & 15;

    const int er   = lane >> 2;
    const int ec   = (lane & 3) * 2;
    const int b_r  = (lane & 7) + (((lane >> 4) & 1) << 3);
    const int b_c8 = ((lane >> 3) & 1) << 3;

    const int k_key = tid >> 3, k_c8 = (tid & 7) * 8;
    const int v_d   = tid >> 2, v_kc = (tid & 3) * 8;
    const size_t kbase = (size_t)(b * SEQ_LEN + k_key) * EMBED_DIM + h * HEAD_DIM + k_c8;
    const size_t vbase = ((size_t)(b * 16 + h) * HEAD_DIM + v_d) * SEQ_LEN + v_kc;
    uint32_t aKhi[2], aKlo[2], aVhi[2], aVlo[2];
    #pragma unroll
    for (int bf = 0; bf < 2; bf++) {
        aKhi[bf] = smem_u32(&sKhi[bf][k_key * KST + k_c8]);
        aKlo[bf] = smem_u32(&sKlo[bf][k_key * KST + k_c8]);
        aVhi[bf] = smem_u32(&sVhi[bf][v_d * VST + v_kc]);
        aVlo[bf] = smem_u32(&sVlo[bf][v_d * VST + v_kc]);
    }

    uint32_t qh[4][4], ql[4][4];
    {
        size_t r0 = (size_t)(b * SEQ_LEN + q0 + wm + er) * EMBED_DIM + h * HEAD_DIM;
        size_t r1 = r0 + 8 * EMBED_DIM;
        #pragma unroll
        for (int c = 0; c < 4; c++) {
            int cc = c * 16 + ec;
            qh[c][0] = *(const uint32_t*)&g_Qhi[r0 + cc];
            qh[c][1] = *(const uint32_t*)&g_Qhi[r1 + cc];
            qh[c][2] = *(const uint32_t*)&g_Qhi[r0 + cc + 8];
            qh[c][3] = *(const uint32_t*)&g_Qhi[r1 + cc + 8];
            ql[c][0] = *(const uint32_t*)&g_Qlo[r0 + cc];
            ql[c][1] = *(const uint32_t*)&g_Qlo[r1 + cc];
            ql[c][2] = *(const uint32_t*)&g_Qlo[r0 + cc + 8];
            ql[c][3] = *(const uint32_t*)&g_Qlo[r1 + cc + 8];
        }
    }

    float m0r = -1e30f, m1r = -1e30f, l0 = 0.f, l1 = 0.f;
    float o[8][4];
    #pragma unroll
    for (int ni = 0; ni < 8; ni++)
        #pragma unroll
        for (int r = 0; r < 4; r++) o[ni][r] = 0.f;

    {
        CPA16(aKhi[0], (const void*)&g_Khi[kbase]);
        CPA16(aKlo[0], (const void*)&g_Klo[kbase]);
        CPA16(aVhi[0], (const void*)&g_Vthi[vbase]);
        CPA16(aVlo[0], (const void*)&g_Vtlo[vbase]);
        CPA_COMMIT();
        if (tid < KT)
            mk[0][tid] = (mask[b * SEQ_LEN + tid] == 0) ? -1e20f : 0.f;
        CPA_WAIT0();
    }
    __syncthreads();

    for (int ti = 0; ti < NT; ti++) {
        const int cur = ti & 1;
        const int nb  = cur ^ 1;
        const bool nx = (ti + 1) < NT;

        int nmv = 1;
        if (nx) {
            size_t kg = kbase + (size_t)(ti + 1) * KT * EMBED_DIM;
            size_t vg = vbase + (size_t)(ti + 1) * KT;
            CPA16(aKhi[nb], (const void*)&g_Khi[kg]);
            CPA16(aKlo[nb], (const void*)&g_Klo[kg]);
            CPA16(aVhi[nb], (const void*)&g_Vthi[vg]);
            CPA16(aVlo[nb], (const void*)&g_Vtlo[vg]);
            CPA_COMMIT();
            if (tid < KT) nmv = mask[b * SEQ_LEN + (ti + 1) * KT + tid];
        }

        float s[4][4];
        #pragma unroll
        for (int j = 0; j < 4; j++)
            #pragma unroll
            for (int r = 0; r < 4; r++) s[j][r] = 0.f;
        #pragma unroll
        for (int c = 0; c < 4; c++) {
            uint32_t bb[4][2];
            #pragma unroll
            for (int np = 0; np < 2; np++) {
                uint32_t ad = smem_u32(&sKhi[cur][(np * 16 + b_r) * KST + c * 16 + b_c8]);
                ldm_x4(bb[2*np][0], bb[2*np][1], bb[2*np+1][0], bb[2*np+1][1], ad);
            }
            #pragma unroll
            for (int j = 0; j < 4; j++) mma16816(s[j], qh[c], bb[j]);
            #pragma unroll
            for (int j = 0; j < 4; j++) mma16816(s[j], ql[c], bb[j]);
            #pragma unroll
            for (int np = 0; np < 2; np++) {
                uint32_t ad = smem_u32(&sKlo[cur][(np * 16 + b_r) * KST + c * 16 + b_c8]);
                ldm_x4(bb[2*np][0], bb[2*np][1], bb[2*np+1][0], bb[2*np+1][1], ad);
            }
            #pragma unroll
            for (int j = 0; j < 4; j++) mma16816(s[j], qh[c], bb[j]);
        }

        #pragma unroll
        for (int j = 0; j < 4; j++) {
            float a0 = mk[cur][j * 8 + ec], a1 = mk[cur][j * 8 + ec + 1];
            s[j][0] += a0; s[j][1] += a1; s[j][2] += a0; s[j][3] += a1;
        }
        float r0 = fmaxf(fmaxf(s[0][0], s[0][1]), fmaxf(s[1][0], s[1][1]));
        r0 = fmaxf(r0, fmaxf(fmaxf(s[2][0], s[2][1]), fmaxf(s[3][0], s[3][1])));
        float r1 = fmaxf(fmaxf(s[0][2], s[0][3]), fmaxf(s[1][2], s[1][3]));
        r1 = fmaxf(r1, fmaxf(fmaxf(s[2][2], s[2][3]), fmaxf(s[3][2], s[3][3])));
        r0 = fmaxf(r0, __shfl_xor_sync(0xffffffffu, r0, 1));
        r0 = fmaxf(r0, __shfl_xor_sync(0xffffffffu, r0, 2));
        r1 = fmaxf(r1, __shfl_xor_sync(0xffffffffu, r1, 1));
        r1 = fmaxf(r1, __shfl_xor_sync(0xffffffffu, r1, 2));
        float mn0 = fmaxf(m0r, r0), mn1 = fmaxf(m1r, r1);
        float al0 = __expf(m0r - mn0), al1 = __expf(m1r - mn1);
        m0r = mn0; m1r = mn1;

        float p[4][4], sum0 = 0.f, sum1 = 0.f;
        #pragma unroll
        for (int j = 0; j < 4; j++) {
            p[j][0] = __expf(s[j][0] - mn0); p[j][1] = __expf(s[j][1] - mn0);
            p[j][2] = __expf(s[j][2] - mn1); p[j][3] = __expf(s[j][3] - mn1);
            sum0 += p[j][0] + p[j][1];
            sum1 += p[j][2] + p[j][3];
        }
        sum0 += __shfl_xor_sync(0xffffffffu, sum0, 1);
        sum0 += __shfl_xor_sync(0xffffffffu, sum0, 2);
        sum1 += __shfl_xor_sync(0xffffffffu, sum1, 1);
        sum1 += __shfl_xor_sync(0xffffffffu, sum1, 2);
        l0 = l0 * al0 + sum0;
        l1 = l1 * al1 + sum1;
        if (!__all_sync(0xffffffffu, (al0 == 1.0f) && (al1 == 1.0f))) {
            #pragma unroll
            for (int ni = 0; ni < 8; ni++) {
                o[ni][0] *= al0; o[ni][1] *= al0; o[ni][2] *= al1; o[ni][3] *= al1;
            }
        }

        uint32_t ph[2][4], pl[2][4];
        #pragma unroll
        for (int c = 0; c < 2; c++) {
            int j0 = 2 * c, j1 = 2 * c + 1;
            split2(p[j0][0], p[j0][1], ph[c][0], pl[c][0]);
            split2(p[j0][2], p[j0][3], ph[c][1], pl[c][1]);
            split2(p[j1][0], p[j1][1], ph[c][2], pl[c][2]);
            split2(p[j1][2], p[j1][3], ph[c][3], pl[c][3]);
        }

        #pragma unroll
        for (int c = 0; c < 2; c++) {
            uint32_t vb[8][2];
            #pragma unroll
            for (int np = 0; np < 4; np++) {
                uint32_t ad = smem_u32(&sVhi[cur][(np * 16 + b_r) * VST + c * 16 + b_c8]);
                ldm_x4(vb[2*np][0], vb[2*np][1], vb[2*np+1][0], vb[2*np+1][1], ad);
            }
            #pragma unroll
            for (int ni = 0; ni < 8; ni++) mma16816(o[ni], ph[c], vb[ni]);
            #pragma unroll
            for (int ni = 0; ni < 8; ni++) mma16816(o[ni], pl[c], vb[ni]);
            #pragma unroll
            for (int np = 0; np < 4; np++) {
                uint32_t ad = smem_u32(&sVlo[cur][(np * 16 + b_r) * VST + c * 16 + b_c8]);
                ldm_x4(vb[2*np][0], vb[2*np][1], vb[2*np+1][0], vb[2*np+1][1], ad);
            }
            #pragma unroll
            for (int ni = 0; ni < 8; ni++) mma16816(o[ni], ph[c], vb[ni]);
        }

        if (nx) {
            CPA_WAIT0();
            if (tid < KT) mk[nb][tid] = (nmv == 0) ? -1e20f : 0.f;
        }
        __syncthreads();
    }

    {
        float i0 = 1.f / l0, i1 = 1.f / l1;
        size_t r0o = (size_t)(b * SEQ_LEN + q0 + wm + er) * EMBED_DIM + h * HEAD_DIM;
        size_t r1o = r0o + 8 * EMBED_DIM;
        #pragma unroll
        for (int ni = 0; ni < 8; ni++) {
            int d = ni * 8 + ec;
            uint32_t hh, ll;
            split2(o[ni][0] * i0, o[ni][1] * i0, hh, ll);
            *(uint32_t*)&g_Ahi[r0o + d] = hh;
            *(uint32_t*)&g_Alo[r0o + d] = ll;
            split2(o[ni][2] * i1, o[ni][3] * i1, hh, ll);
            *(uint32_t*)&g_Ahi[r1o + d] = hh;
            *(uint32_t*)&g_Alo[r1o + d] = ll;
        }
    }
}

// =================================================================================
// kernel_launch: FOUR launches, no runtime API calls.
// =================================================================================
extern "C" void kernel_launch(void* const* d_in, const int* in_sizes, int n_in,
                              void* d_out, int out_size)
{
    const float* values = (const float*)d_in[0];
    const float* keys   = (const float*)d_in[1];
    const float* query  = (const float*)d_in[2];
    const int*   mask   = (const int*)  d_in[3];
    const float* W_q    = (const float*)d_in[4];
    const float* W_k    = (const float*)d_in[5];
    const float* W_v    = (const float*)d_in[6];
    const float* W_o    = (const float*)d_in[7];
    const float* b_o    = (const float*)d_in[8];
    float* out = (float*)d_out;

    wsplit_kernel<<<4096, 256>>>(W_q, W_k, W_v, W_o);

    dim3 qkv_grid(EMBED_DIM / GBN, NTOK / GBM, 3);      // (8, 32, 3) = 768 CTAs
    gemm_mma_kernel<<<qkv_grid, 256>>>(query, keys, values,
                                       nullptr, -1, 0, nullptr);

    dim3 agrid(SEQ_LEN / QT, 2 * 16);                   // 512 CTAs
    attn_kernel<<<agrid, 256>>>(mask);

    dim3 ogrid(EMBED_DIM / GBN, NTOK / GBM);            // 256 CTAs
    gemm_mma_kernel<<<ogrid, 256>>>(nullptr, nullptr, nullptr,
                                    b_o, OUT_EXT, 3, out);
}